// round 8
// baseline (speedup 1.0000x reference)
#include <cuda_runtime.h>
#include <math.h>

// ----------------------------------------------------------------------------
// margin ranking loss (all i<j pairs) + weighted BCE, B=8192, labels in {0,1}.
//   equal-label pairs: relu(m) each -> closed form from n1
//   mixed pairs:       relu((m + p_neg) - p_pos)
// Exact binned algorithm: c = m+p_neg and a = p_pos binned on one value grid.
//   bin(c) < bin(a)  -> c <= a        -> 0            (skipped)
//   bin(c) > bin(a)  -> c >= a        -> (c - a)      (suffix count/sum, O(1)/a)
//   bin(c) == bin(a) -> exact relu vs stored bin list (~90 items avg)
// Edge bins are open-ended and overflow items get exact eval -> exact always.
// ----------------------------------------------------------------------------

#define T1   256
#define T2   256
#define MAXB 8192
#define NBIN 128
#define CAP  512
#define BLO  (-6.0f)
#define BHI  (7.0f)
#define INVW ((float)NBIN / (BHI - BLO))
#define MAXG 64

// scratch (allocation-free rule: __device__ globals)
__device__ int      g_bc[NBIN];            // bin attempt counts
__device__ float    g_bs[NBIN];            // bin sums (stored items only)
__device__ float    g_bins[NBIN * CAP];    // stored c values per bin
__device__ float    g_ovf[MAXB];           // overflow list (normally empty)
__device__ int      g_ovfCnt = 0;
__device__ int      g_n1     = 0;
__device__ double   g_bceB[MAXG];
__device__ double   g_mixB[MAXG];
__device__ unsigned g_done   = 0;

__device__ __forceinline__ float read_margin(const void* p) {
    if (p == nullptr) return 1.0f;
    int v = *(const int*)p;
    if (v >= -1000000 && v <= 1000000) return (float)v;   // int scalar
    return __int_as_float(v);                             // float bits
}

__device__ __forceinline__ int bin_of(float x) {
    int b = (int)floorf((x - BLO) * INVW);
    return max(0, min(NBIN - 1, b));
}

// ---------------------------------------------------------------------------
// Kernel 1: BCE partials, n1 count, binned scatter of c = m + p_neg.
// ---------------------------------------------------------------------------
__global__ void __launch_bounds__(T1)
k1(const float* __restrict__ preds,  const float* __restrict__ labels,
   const float* __restrict__ logits, const float* __restrict__ targets,
   const float* __restrict__ pw_, int n, const void* __restrict__ marginp)
{
    const int tid  = threadIdx.x;
    const int lane = tid & 31, w = tid >> 5;
    const int i    = blockIdx.x * T1 + tid;
    const float m  = read_margin(marginp);
    const float pw = pw_[0];

    float p = 0.f, bce = 0.f;
    bool pos = false, neg = false;
    if (i < n) {
        p = preds[i];
        const bool fl = (labels[i] > 0.5f);
        pos = fl; neg = !fl;
        const float x  = logits[i];
        const float t  = targets[i];
        const float mv = fmaxf(-x, 0.0f);
        const float sp = __logf(__expf(-mv) + __expf(-x - mv)) + mv;
        bce = (1.0f - t) * x + (1.0f + (pw - 1.0f) * t) * sp;
    }

    // n1: one atomic per warp
    const unsigned bp = __ballot_sync(0xffffffffu, pos);
    if (lane == 0 && bp) atomicAdd(&g_n1, __popc(bp));

    // binned scatter of negatives (order in bin irrelevant: sums commute)
    if (neg) {
        const float c  = m + p;
        const int   ib = bin_of(c);
        const int  idx = atomicAdd(&g_bc[ib], 1);
        if (idx < CAP) {
            g_bins[ib * CAP + idx] = c;
            atomicAdd(&g_bs[ib], c);
        } else {
            const int oi = atomicAdd(&g_ovfCnt, 1);
            if (oi < MAXB) g_ovf[oi] = c;
        }
    }

    // BCE block reduce -> one plain store per block
    double d = (double)bce;
    #pragma unroll
    for (int off = 16; off; off >>= 1)
        d += __shfl_down_sync(0xffffffffu, d, off);
    __shared__ double wb[8];
    if (lane == 0) wb[w] = d;
    __syncthreads();
    if (tid == 0) {
        double s = 0.0;
        #pragma unroll
        for (int k = 0; k < 8; k++) s += wb[k];
        g_bceB[blockIdx.x] = s;
    }
}

// ---------------------------------------------------------------------------
// Kernel 2: suffix-scan bins in smem; per-pos closed form + warp-cooperative
// same-bin exact eval; last block finalizes outputs and resets state.
// ---------------------------------------------------------------------------
__global__ void __launch_bounds__(T2)
k2(const float* __restrict__ preds, const float* __restrict__ labels,
   int n, const void* __restrict__ marginp, float* __restrict__ out)
{
    __shared__ double sS[NBIN + 1];
    __shared__ int    sC[NBIN + 1];
    __shared__ int    rawC[NBIN];
    __shared__ double wred[8];
    __shared__ int    isLast;

    const int tid  = threadIdx.x;
    const int lane = tid & 31, w = tid >> 5;
    const float m  = read_margin(marginp);

    // load bins (stored counts) and build suffix sums
    if (tid < NBIN) {
        const int c = min(g_bc[tid], CAP);
        rawC[tid] = c;
        sC[tid]   = c;
        sS[tid]   = (double)g_bs[tid];
    }
    if (tid == NBIN) { sC[NBIN] = 0; sS[NBIN] = 0.0; }
    __syncthreads();
    for (int off = 1; off < NBIN; off <<= 1) {
        double vS = 0.0; int vC = 0;
        if (tid < NBIN && tid + off <= NBIN) { vS = sS[tid + off]; vC = sC[tid + off]; }
        __syncthreads();
        if (tid < NBIN) { sS[tid] += vS; sC[tid] += vC; }
        __syncthreads();
    }

    // per-element phase
    const int i = blockIdx.x * T2 + tid;
    float a = 0.f; bool pos = false; int ka = 0;
    if (i < n) { a = preds[i]; pos = (labels[i] > 0.5f); }

    double dacc = 0.0;
    if (pos) {
        ka   = bin_of(a);
        dacc = sS[ka + 1] - (double)a * (double)sC[ka + 1];   // all higher bins
    }

    // cooperative exact eval: lanes split own-bin list (+overflow, usually 0)
    const int oc = min(g_ovfCnt, MAXB);
    unsigned bm  = __ballot_sync(0xffffffffu, pos);
    float part = 0.f;
    while (bm) {
        const int   k  = __ffs(bm) - 1; bm &= bm - 1u;
        const float aa = __shfl_sync(0xffffffffu, a,  k);
        const int   kb = __shfl_sync(0xffffffffu, ka, k);
        const int  cnt = rawC[kb];
        const int base = kb * CAP;
        for (int j = lane; j < cnt; j += 32)
            part += fmaxf(g_bins[base + j] - aa, 0.f);
        for (int j = lane; j < oc; j += 32)
            part += fmaxf(g_ovf[j] - aa, 0.f);
    }
    dacc += (double)part;

    // block reduce + publish
    #pragma unroll
    for (int off = 16; off; off >>= 1)
        dacc += __shfl_down_sync(0xffffffffu, dacc, off);
    if (lane == 0) wred[w] = dacc;
    __syncthreads();
    if (tid == 0) {
        double s = 0.0;
        #pragma unroll
        for (int k = 0; k < 8; k++) s += wred[k];
        g_mixB[blockIdx.x] = s;
        __threadfence();
        isLast = (atomicAdd(&g_done, 1u) == gridDim.x - 1u) ? 1 : 0;
    }
    __syncthreads();

    // last block: finalize + reset
    if (isLast) {
        const int gb = gridDim.x;
        double fm = 0.0, fb = 0.0;
        for (int j = tid; j < gb; j += T2) {
            fm += __ldcg(&g_mixB[j]);
            fb += __ldcg(&g_bceB[j]);
        }
        #pragma unroll
        for (int off = 16; off; off >>= 1) {
            fm += __shfl_down_sync(0xffffffffu, fm, off);
            fb += __shfl_down_sync(0xffffffffu, fb, off);
        }
        __shared__ double zm[8], zb[8];
        if (lane == 0) { zm[w] = fm; zb[w] = fb; }
        __syncthreads();
        if (tid == 0) {
            double sm = 0.0, sb = 0.0;
            #pragma unroll
            for (int k = 0; k < 8; k++) { sm += zm[k]; sb += zb[k]; }
            const int    n1  = g_n1;
            const double dn1 = (double)n1, dn0 = (double)(n - n1);
            const double eqPairs = 0.5 * (dn1 * (dn1 - 1.0) + dn0 * (dn0 - 1.0));
            const double mm = (m > 0.0f) ? (double)m : 0.0;
            out[0] = (float)((mm * eqPairs + sm) / (double)n);
            out[1] = (float)(sb / (double)n);
        }
        __syncthreads();
        // reset persistent state for next graph replay
        for (int j = tid; j < NBIN; j += T2) { g_bc[j] = 0; g_bs[j] = 0.f; }
        if (tid == 0) { g_ovfCnt = 0; g_n1 = 0; g_done = 0u; }
    }
}

// ---------------------------------------------------------------------------
extern "C" void kernel_launch(void* const* d_in, const int* in_sizes, int n_in,
                              void* d_out, int out_size)
{
    const float* preds   = (const float*)d_in[0];
    const float* labels  = (const float*)d_in[1];
    const float* logits  = (const float*)d_in[2];
    const float* targets = (const float*)d_in[3];
    const float* pw      = (const float*)d_in[4];
    const void*  marginp = (n_in >= 6) ? d_in[5] : nullptr;
    const int n = in_sizes[0];
    float* out = (float*)d_out;

    const int g = min((n + T1 - 1) / T1, MAXG);
    k1<<<g, T1>>>(preds, labels, logits, targets, pw, n, marginp);
    k2<<<g, T2>>>(preds, labels, n, marginp, out);
}